// round 15
// baseline (speedup 1.0000x reference)
#include <cuda_runtime.h>
#include <cuda_fp16.h>
#include <cstdint>

// ---------------- problem dims ----------------
#define NTOK 4096
#define CDIM 1024
#define ENUM 8
#define HDIM 512
#define HSDIM 2048

// ---------------- GEMM tiling (fp16 m16n8k16) ----------------
#define BM 128
#define BKH 64                        // k per tile (halves)
#define AST2 80                       // smem row stride in halves (160B) -> conflict-free LDS.64
#define STGH (BM * AST2)              // 10240 halves = 20480 B per operand stage
#define SMEMB (4 * STGH * 2)          // 81920 B (2 stages x (A+B))

// fp16 k-permutation within each 16-wide k-group:
// storage order [0,1,8,9, 2,3,10,11, 4,5,12,13, 6,7,14,15]
__device__ __forceinline__ int ph16(int c) {
    return (((c & 7) >> 1) << 2) | (((c >> 3) & 1) << 1) | (c & 1);
}

// ---------------- device scratch ----------------
__device__ int    d_cnt[ENUM];
__device__ int    d_tok[ENUM][NTOK];
__device__ float  d_gate[ENUM][NTOK];
__device__ int    d_eslot[NTOK][2];
__device__ __half d_hid [ENUM*NTOK*HDIM];    // fp16 perm hidden
__device__ __half d_pairh[ENUM*NTOK*CDIM];   // gate-scaled expert out (fp16 canonical)
__device__ __half d_sh  [NTOK*HSDIM];        // fp16 perm shared hidden
__device__ __half d_xr  [NTOK*CDIM];         // fp16 perm x
__device__ __half d_guT [ENUM*2*HDIM*CDIM];  // [E][2H][C] transposed, fp16 perm
__device__ __half d_dwT [ENUM*CDIM*HDIM];    // [E][C][H] transposed, fp16 perm
__device__ __half d_sgwr[HSDIM*CDIM];        // fp16 perm
__device__ __half d_suwr[HSDIM*CDIM];        // fp16 perm
__device__ __half d_sdwr[CDIM*HSDIM];        // fp16 perm

// ---------------- helpers ----------------
__device__ __forceinline__ void cp16(__half* s, const __half* g) {
    uint32_t sa = (uint32_t)__cvta_generic_to_shared(s);
    asm volatile("cp.async.cg.shared.global [%0], [%1], 16;" :: "r"(sa), "l"(g));
}
__device__ __forceinline__ void mma16(float* d, const uint32_t* a, const uint32_t* b) {
    asm volatile(
        "mma.sync.aligned.m16n8k16.row.col.f32.f16.f16.f32 "
        "{%0,%1,%2,%3},{%4,%5,%6,%7},{%8,%9},{%0,%1,%2,%3};"
        : "+f"(d[0]), "+f"(d[1]), "+f"(d[2]), "+f"(d[3])
        : "r"(a[0]), "r"(a[1]), "r"(a[2]), "r"(a[3]), "r"(b[0]), "r"(b[1]));
}
__device__ __forceinline__ float silu_f(float v) { return v / (1.f + expf(-v)); }
__device__ __forceinline__ uint32_t h2u(float a, float b) {
    __half2 h = __floats2half2_rn(a, b);
    return *(uint32_t*)&h;
}
__device__ __forceinline__ float dot4(float4 a, float4 b) {
    return a.x * b.x + a.y * b.y + a.z * b.z + a.w * b.w;
}

// ---------------- router: 4 tokens/warp, rw amortized across tokens -------------
// block = 128 threads (4 warps), each warp handles 4 tokens; lane covers 32 floats.
__global__ __launch_bounds__(128) void router_kernel(
    const float* __restrict__ x, const float* __restrict__ rw, __half* __restrict__ xw)
{
    const int wid = threadIdx.x >> 5, lane = threadIdx.x & 31;
    const int t0 = (blockIdx.x * 4 + wid) * 4;

    // load x for 4 tokens (lane's 32 floats = 16-groups 2*lane, 2*lane+1)
    float4 xv[4][8];
#pragma unroll
    for (int tt = 0; tt < 4; tt++) {
        const float4* x4 = (const float4*)(x + (long long)(t0 + tt) * CDIM);
#pragma unroll
        for (int j = 0; j < 8; j++) xv[tt][j] = x4[lane * 8 + j];
    }

    // expert-outer: rw chunk loaded once, reused by all 4 tokens
    float acc[4][ENUM];
#pragma unroll
    for (int e = 0; e < ENUM; e++) {
        const float4* w4 = (const float4*)(rw + e * CDIM);
        float4 wv[8];
#pragma unroll
        for (int j = 0; j < 8; j++) wv[j] = w4[lane * 8 + j];
#pragma unroll
        for (int tt = 0; tt < 4; tt++) {
            float s = 0.f;
#pragma unroll
            for (int j = 0; j < 8; j++) s += dot4(xv[tt][j], wv[j]);
            acc[tt][e] = s;
        }
    }

    // fp16 perm stores (both 16-groups per token)
#pragma unroll
    for (int tt = 0; tt < 4; tt++) {
        uint4* xo = (uint4*)(xw + (long long)(t0 + tt) * CDIM);
#pragma unroll
        for (int g = 0; g < 2; g++) {
            float4 v0 = xv[tt][4 * g], v1 = xv[tt][4 * g + 1];
            float4 v2 = xv[tt][4 * g + 2], v3 = xv[tt][4 * g + 3];
            uint4 o0, o1;
            o0.x = h2u(v0.x, v0.y); o0.y = h2u(v2.x, v2.y);
            o0.z = h2u(v0.z, v0.w); o0.w = h2u(v2.z, v2.w);
            o1.x = h2u(v1.x, v1.y); o1.y = h2u(v3.x, v3.y);
            o1.z = h2u(v1.z, v1.w); o1.w = h2u(v3.z, v3.w);
            xo[lane * 4 + 2 * g]     = o0;
            xo[lane * 4 + 2 * g + 1] = o1;
        }
    }

    // reduce + top2 per token
#pragma unroll
    for (int tt = 0; tt < 4; tt++)
#pragma unroll
        for (int e = 0; e < ENUM; e++)
#pragma unroll
            for (int off = 16; off; off >>= 1)
                acc[tt][e] += __shfl_xor_sync(~0u, acc[tt][e], off);
    if (lane == 0) {
#pragma unroll
        for (int tt = 0; tt < 4; tt++) {
            int t = t0 + tt;
            int i0 = 0; float v0m = acc[tt][0];
#pragma unroll
            for (int e = 1; e < ENUM; e++) if (acc[tt][e] > v0m) { v0m = acc[tt][e]; i0 = e; }
            int i1 = -1; float v1m = -3.0e38f;
#pragma unroll
            for (int e = 0; e < ENUM; e++) if (e != i0 && acc[tt][e] > v1m) { v1m = acc[tt][e]; i1 = e; }
            float g0 = 1.f / (1.f + expf(-v0m));
            float g1 = 1.f / (1.f + expf(-v1m));
            int s0 = atomicAdd(&d_cnt[i0], 1);
            int s1 = atomicAdd(&d_cnt[i1], 1);
            d_tok[i0][s0] = t; d_gate[i0][s0] = g0; d_eslot[t][0] = i0 * NTOK + s0;
            d_tok[i1][s1] = t; d_gate[i1][s1] = g1; d_eslot[t][1] = i1 * NTOK + s1;
        }
    }
}

// ---------------- preprocessing ----------------
__global__ void round_perm3(const float* __restrict__ s0, __half* __restrict__ d0,
                            const float* __restrict__ s1, __half* __restrict__ d1,
                            const float* __restrict__ s2, __half* __restrict__ d2) {
    const float* src = (blockIdx.y == 0) ? s0 : (blockIdx.y == 1) ? s1 : s2;
    __half*      dst = (blockIdx.y == 0) ? d0 : (blockIdx.y == 1) ? d1 : d2;
    long long g = (long long)blockIdx.x * 256 + threadIdx.x;
    const float4* s4 = (const float4*)src;
    float4 v0 = s4[4 * g], v1 = s4[4 * g + 1], v2 = s4[4 * g + 2], v3 = s4[4 * g + 3];
    uint4 o0, o1;
    o0.x = h2u(v0.x, v0.y); o0.y = h2u(v2.x, v2.y);
    o0.z = h2u(v0.z, v0.w); o0.w = h2u(v2.z, v2.w);
    o1.x = h2u(v1.x, v1.y); o1.y = h2u(v3.x, v3.y);
    o1.z = h2u(v1.z, v1.w); o1.w = h2u(v3.z, v3.w);
    ((uint4*)dst)[2 * g] = o0; ((uint4*)dst)[2 * g + 1] = o1;
}
__global__ void transpose_h_perm(const float* __restrict__ src, __half* __restrict__ dst,
                                 int R, int C) {
    __shared__ float tile[32][33];
    long long zi = (long long)blockIdx.z * R * C;
    int r0 = blockIdx.y * 32, c0 = blockIdx.x * 32;
    int tx = threadIdx.x, ty = threadIdx.y;
#pragma unroll
    for (int i = 0; i < 32; i += 8)
        tile[ty + i][tx] = src[zi + (long long)(r0 + ty + i) * C + c0 + tx];
    __syncthreads();
    int rp = r0 + (tx & 16) + ph16(tx & 15);
#pragma unroll
    for (int i = 0; i < 32; i += 8)
        dst[zi + (long long)(c0 + ty + i) * R + rp] = __float2half_rn(tile[tx][ty + i]);
}

// ---------------- phase 1: fused SwiGLU GEMMs (fp16, templated expert/shared) ---
template <bool EXPERT>
__global__ __launch_bounds__(128) void phase1_kernel(
    const __half* __restrict__ xr, const __half* __restrict__ guT,
    const __half* __restrict__ sgw, const __half* __restrict__ suw,
    __half* __restrict__ hid, __half* __restrict__ sh)
{
    const int bid = blockIdx.x;
    const __half *B1, *B2;
    __half* C; int ldc, z = 0, bm, bn;
    if (EXPERT) {
        z = bid >> 8; int rem = bid & 255; bm = rem >> 3; bn = rem & 7;
        if (bm * BM >= d_cnt[z]) return;
        B1 = guT + (long long)z * 2 * HDIM * CDIM + (long long)(bn * 64) * CDIM;
        B2 = B1 + (long long)HDIM * CDIM;
        C  = hid + (long long)z * NTOK * HDIM;
        ldc = HDIM;
    } else {
        bm = bid >> 5; bn = bid & 31;
        B1 = sgw + (long long)(bn * 64) * CDIM;
        B2 = suw + (long long)(bn * 64) * CDIM;
        C  = sh;
        ldc = HSDIM;
    }
    const int K = CDIM;

    extern __shared__ __align__(16) __half smem[];
    __half* sA = smem;
    __half* sB = smem + 2 * STGH;

    const int tid = threadIdx.x, lane = tid & 31, w = tid >> 5;
    const int ly = lane >> 2, lx = lane & 3;
    const int wm = w >> 1, wn = w & 1;

    const __half* aPtr[8];
    const __half* bPtr[8];
    const int rbase = tid >> 3, kc = (tid & 7) * 8;
#pragma unroll
    for (int c = 0; c < 8; c++) {
        int row = rbase + 16 * c;
        long long arow = EXPERT ? (long long)d_tok[z][bm * BM + row] : (long long)(bm * BM + row);
        aPtr[c] = xr + arow * K;
        bPtr[c] = ((row < 64) ? (B1 + (long long)row * K) : (B2 + (long long)(row - 64) * K));
    }
    auto loadStage = [&](int st, int k0) {
        __half* dA = sA + st * STGH;
        __half* dB = sB + st * STGH;
#pragma unroll
        for (int c = 0; c < 8; c++) {
            int row = rbase + 16 * c;
            cp16(dA + row * AST2 + kc, aPtr[c] + k0 + kc);
            cp16(dB + row * AST2 + kc, bPtr[c] + k0 + kc);
        }
        asm volatile("cp.async.commit_group;");
    };

    float accG[4][4][4], accU[4][4][4];
#pragma unroll
    for (int a = 0; a < 4; a++)
#pragma unroll
        for (int b = 0; b < 4; b++)
#pragma unroll
            for (int q = 0; q < 4; q++) { accG[a][b][q] = 0.f; accU[a][b][q] = 0.f; }

    const int nk = K / BKH;
    loadStage(0, 0);

    for (int kt = 0; kt < nk; kt++) {
        const int st = kt & 1;
        asm volatile("cp.async.wait_group 0;");
        __syncthreads();
        if (kt + 1 < nk) loadStage((kt + 1) & 1, (kt + 1) * BKH);

        const __half* cA = sA + st * STGH;
        const __half* cB = sB + st * STGH;
#pragma unroll
        for (int kg = 0; kg < 4; kg++) {
            const int kb = kg * 16 + lx * 4;
            uint32_t af[4][4], bg[4][2], bu[4][2];
#pragma unroll
            for (int im = 0; im < 4; im++) {
                int r = wm * 64 + im * 16;
                uint2 v0 = *(const uint2*)(cA + (r     + ly) * AST2 + kb);
                uint2 v1 = *(const uint2*)(cA + (r + 8 + ly) * AST2 + kb);
                af[im][0] = v0.x; af[im][1] = v1.x; af[im][2] = v0.y; af[im][3] = v1.y;
            }
#pragma unroll
            for (int in = 0; in < 4; in++) {
                int cn = wn * 32 + in * 8 + ly;
                uint2 g = *(const uint2*)(cB + cn * AST2 + kb);
                uint2 u = *(const uint2*)(cB + (64 + cn) * AST2 + kb);
                bg[in][0] = g.x; bg[in][1] = g.y;
                bu[in][0] = u.x; bu[in][1] = u.y;
            }
#pragma unroll
            for (int im = 0; im < 4; im++)
#pragma unroll
                for (int in = 0; in < 4; in++) {
                    mma16(accG[im][in], af[im], bg[in]);
                    mma16(accU[im][in], af[im], bu[in]);
                }
        }
    }

    // epilogue: out = fp16(silu(g)*u), perm16 layout
#pragma unroll
    for (int im = 0; im < 4; im++) {
        int rr = bm * BM + wm * 64 + im * 16 + ly;
#pragma unroll
        for (int in = 0; in < 4; in++) {
            int G   = wn * 2 + (in >> 1);
            int pos = lx * 4 + (in & 1) * 2;
            long long off = (long long)rr * ldc + bn * 64 + G * 16 + pos;
            float* g = accG[im][in];
            float* u = accU[im][in];
            *(uint32_t*)(C + off)             = h2u(silu_f(g[0]) * u[0], silu_f(g[1]) * u[1]);
            *(uint32_t*)(C + off + 8LL * ldc) = h2u(silu_f(g[2]) * u[2], silu_f(g[3]) * u[3]);
        }
    }
}

// ---------------- phase 2: down GEMMs (fp16, templated expert/shared) ------------
// EXPERT: writes fp16 pair (gate-scaled); shared: writes fp32 out.
template <bool EXPERT>
__global__ __launch_bounds__(128) void phase2_kernel(
    const __half* __restrict__ hid, const __half* __restrict__ dwT,
    const __half* __restrict__ sh,  const __half* __restrict__ sdw,
    __half* __restrict__ pairh, float* __restrict__ out)
{
    const int bid = blockIdx.x;
    const __half *A, *B; const float* gate;
    __half* Ch = nullptr; float* Cf = nullptr;
    int K, z = 0, bm, bn;
    if (EXPERT) {
        z = bid >> 8; int rem = bid & 255; bm = rem >> 3; bn = rem & 7;
        if (bm * BM >= d_cnt[z]) return;
        A = hid + (long long)z * NTOK * HDIM;
        K = HDIM;
        B = dwT + (long long)z * CDIM * HDIM + (long long)(bn * 128) * HDIM;
        Ch = pairh + (long long)z * NTOK * CDIM;
        gate = d_gate[z];
    } else {
        bm = bid >> 3; bn = bid & 7;
        A = sh; K = HSDIM;
        B = sdw + (long long)(bn * 128) * HSDIM;
        Cf = out;
        gate = nullptr;
    }

    extern __shared__ __align__(16) __half smem[];
    __half* sA = smem;
    __half* sB = smem + 2 * STGH;

    const int tid = threadIdx.x, lane = tid & 31, w = tid >> 5;
    const int ly = lane >> 2, lx = lane & 3;
    const int wm = w >> 1, wn = w & 1;

    const int rbase = tid >> 3, kc = (tid & 7) * 8;
    const __half* aBase = A + (long long)(bm * BM + rbase) * K;
    const __half* bBase = B + (long long)rbase * K;

    auto loadStage = [&](int st, int k0) {
        __half* dA = sA + st * STGH;
        __half* dB = sB + st * STGH;
#pragma unroll
        for (int c = 0; c < 8; c++) {
            int row = rbase + 16 * c;
            cp16(dA + row * AST2 + kc, aBase + (long long)(16 * c) * K + k0 + kc);
            cp16(dB + row * AST2 + kc, bBase + (long long)(16 * c) * K + k0 + kc);
        }
        asm volatile("cp.async.commit_group;");
    };

    float acc[4][8][4];
#pragma unroll
    for (int a = 0; a < 4; a++)
#pragma unroll
        for (int b = 0; b < 8; b++)
#pragma unroll
            for (int q = 0; q < 4; q++) acc[a][b][q] = 0.f;

    const int nk = K / BKH;
    loadStage(0, 0);

    for (int kt = 0; kt < nk; kt++) {
        const int st = kt & 1;
        asm volatile("cp.async.wait_group 0;");
        __syncthreads();
        if (kt + 1 < nk) loadStage((kt + 1) & 1, (kt + 1) * BKH);

        const __half* cA = sA + st * STGH;
        const __half* cB = sB + st * STGH;
#pragma unroll
        for (int kg = 0; kg < 4; kg++) {
            const int kb = kg * 16 + lx * 4;
            uint32_t af[4][4], bf[8][2];
#pragma unroll
            for (int im = 0; im < 4; im++) {
                int r = wm * 64 + im * 16;
                uint2 v0 = *(const uint2*)(cA + (r     + ly) * AST2 + kb);
                uint2 v1 = *(const uint2*)(cA + (r + 8 + ly) * AST2 + kb);
                af[im][0] = v0.x; af[im][1] = v1.x; af[im][2] = v0.y; af[im][3] = v1.y;
            }
#pragma unroll
            for (int in = 0; in < 8; in++) {
                int cn = wn * 64 + in * 8 + ly;
                uint2 bb = *(const uint2*)(cB + cn * AST2 + kb);
                bf[in][0] = bb.x; bf[in][1] = bb.y;
            }
#pragma unroll
            for (int im = 0; im < 4; im++)
#pragma unroll
                for (int in = 0; in < 8; in++)
                    mma16(acc[im][in], af[im], bf[in]);
        }
    }

#pragma unroll
    for (int im = 0; im < 4; im++) {
        int rr = bm * BM + wm * 64 + im * 16 + ly;
        float s0 = gate ? gate[rr] : 1.f;
        float s1 = gate ? gate[rr + 8] : 1.f;
#pragma unroll
        for (int in = 0; in < 8; in++) {
            long long base = (long long)rr * CDIM + bn * 128 + wn * 64 + in * 8 + lx * 2;
            if (EXPERT) {
                *(uint32_t*)(Ch + base)              = h2u(acc[im][in][0] * s0, acc[im][in][1] * s0);
                *(uint32_t*)(Ch + base + 8LL * CDIM) = h2u(acc[im][in][2] * s1, acc[im][in][3] * s1);
            } else {
                *(float2*)(Cf + base)              = make_float2(acc[im][in][0], acc[im][in][1]);
                *(float2*)(Cf + base + 8LL * CDIM) = make_float2(acc[im][in][2], acc[im][in][3]);
            }
        }
    }
}

// ---------------- final combine: out += gated expert pair (fp16 pair) -----------
__global__ void combine_kernel(float* __restrict__ out, const __half* __restrict__ ph) {
    long long i = (long long)blockIdx.x * 256 + threadIdx.x;   // float4 over out
    int t = (int)(i >> 8), j = (int)(i & 255);
    int es0 = d_eslot[t][0], es1 = d_eslot[t][1];
    float4 o = ((float4*)out)[i];
    uint2 q0 = ((const uint2*)(ph + (long long)es0 * CDIM))[j];
    uint2 q1 = ((const uint2*)(ph + (long long)es1 * CDIM))[j];
    float2 a0 = __half22float2(*(__half2*)&q0.x), b0 = __half22float2(*(__half2*)&q0.y);
    float2 a1 = __half22float2(*(__half2*)&q1.x), b1 = __half22float2(*(__half2*)&q1.y);
    o.x += a0.x + a1.x; o.y += a0.y + a1.y;
    o.z += b0.x + b1.x; o.w += b0.y + b1.y;
    ((float4*)out)[i] = o;
}

// ---------------- launch ----------------
extern "C" void kernel_launch(void* const* d_in, const int* in_sizes, int n_in,
                              void* d_out, int out_size) {
    const float* x   = (const float*)d_in[0];
    const float* rw  = (const float*)d_in[1];
    const float* guw = (const float*)d_in[2];
    const float* dw  = (const float*)d_in[3];
    const float* sgw = (const float*)d_in[4];
    const float* suw = (const float*)d_in[5];
    const float* sdw = (const float*)d_in[6];
    float* out = (float*)d_out;

    void* a;
    __half *p_hid, *p_pairh, *p_sh, *p_xr, *p_guT, *p_dwT, *p_sgwr, *p_suwr, *p_sdwr;
    cudaGetSymbolAddress(&a, d_hid);   p_hid   = (__half*)a;
    cudaGetSymbolAddress(&a, d_pairh); p_pairh = (__half*)a;
    cudaGetSymbolAddress(&a, d_sh);    p_sh    = (__half*)a;
    cudaGetSymbolAddress(&a, d_xr);    p_xr    = (__half*)a;
    cudaGetSymbolAddress(&a, d_guT);   p_guT   = (__half*)a;
    cudaGetSymbolAddress(&a, d_dwT);   p_dwT   = (__half*)a;
    cudaGetSymbolAddress(&a, d_sgwr);  p_sgwr  = (__half*)a;
    cudaGetSymbolAddress(&a, d_suwr);  p_suwr  = (__half*)a;
    cudaGetSymbolAddress(&a, d_sdwr);  p_sdwr  = (__half*)a;
    void* cntAddr; cudaGetSymbolAddress(&cntAddr, d_cnt);

    static cudaStream_t s1 = nullptr, s2 = nullptr;
    static cudaEvent_t ev0 = nullptr, evG = nullptr, evD = nullptr, evP = nullptr,
                       evR = nullptr, evS = nullptr;
    if (!s1) {
        cudaStreamCreateWithFlags(&s1, cudaStreamNonBlocking);
        cudaStreamCreateWithFlags(&s2, cudaStreamNonBlocking);
        cudaEventCreateWithFlags(&ev0, cudaEventDisableTiming);
        cudaEventCreateWithFlags(&evG, cudaEventDisableTiming);
        cudaEventCreateWithFlags(&evD, cudaEventDisableTiming);
        cudaEventCreateWithFlags(&evP, cudaEventDisableTiming);
        cudaEventCreateWithFlags(&evR, cudaEventDisableTiming);
        cudaEventCreateWithFlags(&evS, cudaEventDisableTiming);
        cudaFuncSetAttribute(phase1_kernel<true >, cudaFuncAttributeMaxDynamicSharedMemorySize, SMEMB);
        cudaFuncSetAttribute(phase1_kernel<false>, cudaFuncAttributeMaxDynamicSharedMemorySize, SMEMB);
        cudaFuncSetAttribute(phase2_kernel<true >, cudaFuncAttributeMaxDynamicSharedMemorySize, SMEMB);
        cudaFuncSetAttribute(phase2_kernel<false>, cudaFuncAttributeMaxDynamicSharedMemorySize, SMEMB);
    }

    // ---- fork point ----
    cudaEventRecord(ev0, 0);
    cudaStreamWaitEvent(s1, ev0, 0);

    // side stream s1: ordered so earliest consumers unblock first
    transpose_h_perm<<<dim3(2 * HDIM / 32, CDIM / 32, ENUM), dim3(32, 8), 0, s1>>>(guw, p_guT, CDIM, 2 * HDIM);
    cudaEventRecord(evG, s1);
    round_perm3<<<dim3(HSDIM * CDIM / 16 / 256, 3), 256, 0, s1>>>(sgw, p_sgwr, suw, p_suwr, sdw, p_sdwr);
    cudaEventRecord(evP, s1);
    transpose_h_perm<<<dim3(CDIM / 32, HDIM / 32, ENUM), dim3(32, 8), 0, s1>>>(dw, p_dwT, HDIM, CDIM);
    cudaEventRecord(evD, s1);

    // main stream: router (emits fp16-perm x + routing tables)
    cudaMemsetAsync(cntAddr, 0, sizeof(int) * ENUM, 0);
    router_kernel<<<NTOK / 16, 128, 0, 0>>>(x, rw, p_xr);
    cudaEventRecord(evR, 0);

    // expert chain on main stream: p1e -> p2e
    cudaStreamWaitEvent(0, evG, 0);
    phase1_kernel<true><<<2048, 128, SMEMB, 0>>>(p_xr, p_guT, p_sgwr, p_suwr, p_hid, p_sh);
    cudaStreamWaitEvent(0, evD, 0);
    phase2_kernel<true><<<2048, 128, SMEMB, 0>>>(p_hid, p_dwT, p_sh, p_sdwr, p_pairh, out);

    // shared chain on s2: p1s -> p2s (writes out base)
    cudaStreamWaitEvent(s2, evR, 0);
    cudaStreamWaitEvent(s2, evP, 0);
    phase1_kernel<false><<<1024, 128, SMEMB, s2>>>(p_xr, p_guT, p_sgwr, p_suwr, p_hid, p_sh);
    phase2_kernel<false><<<256, 128, SMEMB, s2>>>(p_hid, p_dwT, p_sh, p_sdwr, p_pairh, out);
    cudaEventRecord(evS, s2);

    // ---- join: combine after both chains ----
    cudaStreamWaitEvent(0, evS, 0);
    combine_kernel<<<NTOK * CDIM / 4 / 256, 256, 0, 0>>>(out, p_pairh);

    (void)in_sizes; (void)n_in; (void)out_size;
}

// round 16
// speedup vs baseline: 1.0142x; 1.0142x over previous
#include <cuda_runtime.h>
#include <cuda_fp16.h>
#include <cstdint>

// ---------------- problem dims ----------------
#define NTOK 4096
#define CDIM 1024
#define ENUM 8
#define HDIM 512
#define HSDIM 2048

// ---------------- GEMM tiling (fp16 m16n8k16) ----------------
#define BM 128
#define BKH 64                        // k per tile (halves)
#define AST2 80                       // smem row stride in halves (160B) -> conflict-free LDS.64
#define STGH (BM * AST2)              // 10240 halves = 20480 B per operand stage
#define SMEMB (4 * STGH * 2)          // 81920 B (2 stages x (A+B))

// fp16 k-permutation within each 16-wide k-group:
// storage order [0,1,8,9, 2,3,10,11, 4,5,12,13, 6,7,14,15]
__device__ __forceinline__ int ph16(int c) {
    return (((c & 7) >> 1) << 2) | (((c >> 3) & 1) << 1) | (c & 1);
}

// ---------------- device scratch ----------------
__device__ int    d_cnt[ENUM];
__device__ int    d_tok[ENUM][NTOK];
__device__ float  d_gate[ENUM][NTOK];
__device__ int    d_eslot[NTOK][2];
__device__ __half d_hid [ENUM*NTOK*HDIM];    // fp16 perm hidden
__device__ __half d_pairh[ENUM*NTOK*CDIM];   // gate-scaled expert out (fp16 canonical)
__device__ __half d_sh  [NTOK*HSDIM];        // fp16 perm shared hidden
__device__ __half d_xr  [NTOK*CDIM];         // fp16 perm x
__device__ __half d_guT [ENUM*2*HDIM*CDIM];  // [E][2H][C] transposed, fp16 perm
__device__ __half d_dwT [ENUM*CDIM*HDIM];    // [E][C][H] transposed, fp16 perm
__device__ __half d_sgwr[HSDIM*CDIM];        // fp16 perm
__device__ __half d_suwr[HSDIM*CDIM];        // fp16 perm
__device__ __half d_sdwr[CDIM*HSDIM];        // fp16 perm

// ---------------- helpers ----------------
__device__ __forceinline__ void cp16(__half* s, const __half* g) {
    uint32_t sa = (uint32_t)__cvta_generic_to_shared(s);
    asm volatile("cp.async.cg.shared.global [%0], [%1], 16;" :: "r"(sa), "l"(g));
}
__device__ __forceinline__ void mma16(float* d, const uint32_t* a, const uint32_t* b) {
    asm volatile(
        "mma.sync.aligned.m16n8k16.row.col.f32.f16.f16.f32 "
        "{%0,%1,%2,%3},{%4,%5,%6,%7},{%8,%9},{%0,%1,%2,%3};"
        : "+f"(d[0]), "+f"(d[1]), "+f"(d[2]), "+f"(d[3])
        : "r"(a[0]), "r"(a[1]), "r"(a[2]), "r"(a[3]), "r"(b[0]), "r"(b[1]));
}
__device__ __forceinline__ float silu_f(float v) { return v / (1.f + expf(-v)); }
__device__ __forceinline__ uint32_t h2u(float a, float b) {
    __half2 h = __floats2half2_rn(a, b);
    return *(uint32_t*)&h;
}
__device__ __forceinline__ float dot4(float4 a, float4 b) {
    return a.x * b.x + a.y * b.y + a.z * b.z + a.w * b.w;
}

// ---------------- router: smem-staged rw, 32 tokens/CTA, streamed x --------------
// block = 256 threads (8 warps), each warp handles 4 tokens; lane covers 32 floats.
// rw (8x1024 fp32 = 32KB) staged once per CTA with XOR granule swizzle.
__global__ __launch_bounds__(256) void router_kernel(
    const float* __restrict__ x, const float* __restrict__ rw, __half* __restrict__ xw)
{
    __shared__ float4 srw[ENUM * 256];   // granule (e, l, j) at e*256 + l*8 + (j ^ (l&7))
    const int tid = threadIdx.x, wid = tid >> 5, lane = tid & 31;

    // stage rw (coalesced gmem reads, swizzled smem writes)
#pragma unroll
    for (int i = tid; i < ENUM * 256; i += 256) {
        int e = i >> 8, g = i & 255;
        int l = g >> 3, j = g & 7;
        srw[(e << 8) | (l << 3) | (j ^ (l & 7))] = ((const float4*)(rw + e * CDIM))[g];
    }
    __syncthreads();

    const int t0 = (blockIdx.x * 8 + wid) * 4;
    float acc[4][ENUM];
#pragma unroll
    for (int tt = 0; tt < 4; tt++)
#pragma unroll
        for (int e = 0; e < ENUM; e++) acc[tt][e] = 0.f;

    const int lbase = (lane << 3);        // granule base l*8 within an expert row
    const int lx7 = lane & 7;

#pragma unroll
    for (int grp = 0; grp < 2; grp++) {
        // load 4 chunks (float4) x 4 tokens
        float4 xv[4][4];
#pragma unroll
        for (int tt = 0; tt < 4; tt++) {
            const float4* x4 = (const float4*)(x + (long long)(t0 + tt) * CDIM);
#pragma unroll
            for (int c = 0; c < 4; c++) xv[tt][c] = x4[lane * 8 + grp * 4 + c];
        }
        // logits: rw from smem, reused across the 4 tokens
#pragma unroll
        for (int e = 0; e < ENUM; e++) {
            float4 wv[4];
#pragma unroll
            for (int c = 0; c < 4; c++)
                wv[c] = srw[(e << 8) | lbase | ((grp * 4 + c) ^ lx7)];
#pragma unroll
            for (int tt = 0; tt < 4; tt++)
                acc[tt][e] += dot4(xv[tt][0], wv[0]) + dot4(xv[tt][1], wv[1])
                            + dot4(xv[tt][2], wv[2]) + dot4(xv[tt][3], wv[3]);
        }
        // fp16 perm store for this 16-group
#pragma unroll
        for (int tt = 0; tt < 4; tt++) {
            float4 v0 = xv[tt][0], v1 = xv[tt][1], v2 = xv[tt][2], v3 = xv[tt][3];
            uint4 o0, o1;
            o0.x = h2u(v0.x, v0.y); o0.y = h2u(v2.x, v2.y);
            o0.z = h2u(v0.z, v0.w); o0.w = h2u(v2.z, v2.w);
            o1.x = h2u(v1.x, v1.y); o1.y = h2u(v3.x, v3.y);
            o1.z = h2u(v1.z, v1.w); o1.w = h2u(v3.z, v3.w);
            uint4* xo = (uint4*)(xw + (long long)(t0 + tt) * CDIM);
            xo[lane * 4 + grp * 2]     = o0;
            xo[lane * 4 + grp * 2 + 1] = o1;
        }
    }

    // reduce + top2 per token
#pragma unroll
    for (int tt = 0; tt < 4; tt++)
#pragma unroll
        for (int e = 0; e < ENUM; e++)
#pragma unroll
            for (int off = 16; off; off >>= 1)
                acc[tt][e] += __shfl_xor_sync(~0u, acc[tt][e], off);
    if (lane == 0) {
#pragma unroll
        for (int tt = 0; tt < 4; tt++) {
            int t = t0 + tt;
            int i0 = 0; float v0m = acc[tt][0];
#pragma unroll
            for (int e = 1; e < ENUM; e++) if (acc[tt][e] > v0m) { v0m = acc[tt][e]; i0 = e; }
            int i1 = -1; float v1m = -3.0e38f;
#pragma unroll
            for (int e = 0; e < ENUM; e++) if (e != i0 && acc[tt][e] > v1m) { v1m = acc[tt][e]; i1 = e; }
            float g0 = 1.f / (1.f + expf(-v0m));
            float g1 = 1.f / (1.f + expf(-v1m));
            int s0 = atomicAdd(&d_cnt[i0], 1);
            int s1 = atomicAdd(&d_cnt[i1], 1);
            d_tok[i0][s0] = t; d_gate[i0][s0] = g0; d_eslot[t][0] = i0 * NTOK + s0;
            d_tok[i1][s1] = t; d_gate[i1][s1] = g1; d_eslot[t][1] = i1 * NTOK + s1;
        }
    }
}

// ---------------- preprocessing ----------------
__global__ void round_perm3(const float* __restrict__ s0, __half* __restrict__ d0,
                            const float* __restrict__ s1, __half* __restrict__ d1,
                            const float* __restrict__ s2, __half* __restrict__ d2) {
    const float* src = (blockIdx.y == 0) ? s0 : (blockIdx.y == 1) ? s1 : s2;
    __half*      dst = (blockIdx.y == 0) ? d0 : (blockIdx.y == 1) ? d1 : d2;
    long long g = (long long)blockIdx.x * 256 + threadIdx.x;
    const float4* s4 = (const float4*)src;
    float4 v0 = s4[4 * g], v1 = s4[4 * g + 1], v2 = s4[4 * g + 2], v3 = s4[4 * g + 3];
    uint4 o0, o1;
    o0.x = h2u(v0.x, v0.y); o0.y = h2u(v2.x, v2.y);
    o0.z = h2u(v0.z, v0.w); o0.w = h2u(v2.z, v2.w);
    o1.x = h2u(v1.x, v1.y); o1.y = h2u(v3.x, v3.y);
    o1.z = h2u(v1.z, v1.w); o1.w = h2u(v3.z, v3.w);
    ((uint4*)dst)[2 * g] = o0; ((uint4*)dst)[2 * g + 1] = o1;
}
__global__ void transpose_h_perm(const float* __restrict__ src, __half* __restrict__ dst,
                                 int R, int C) {
    __shared__ float tile[32][33];
    long long zi = (long long)blockIdx.z * R * C;
    int r0 = blockIdx.y * 32, c0 = blockIdx.x * 32;
    int tx = threadIdx.x, ty = threadIdx.y;
#pragma unroll
    for (int i = 0; i < 32; i += 8)
        tile[ty + i][tx] = src[zi + (long long)(r0 + ty + i) * C + c0 + tx];
    __syncthreads();
    int rp = r0 + (tx & 16) + ph16(tx & 15);
#pragma unroll
    for (int i = 0; i < 32; i += 8)
        dst[zi + (long long)(c0 + ty + i) * R + rp] = __float2half_rn(tile[tx][ty + i]);
}

// ---------------- phase 1: fused SwiGLU GEMMs (fp16, templated expert/shared) ---
template <bool EXPERT>
__global__ __launch_bounds__(128) void phase1_kernel(
    const __half* __restrict__ xr, const __half* __restrict__ guT,
    const __half* __restrict__ sgw, const __half* __restrict__ suw,
    __half* __restrict__ hid, __half* __restrict__ sh)
{
    const int bid = blockIdx.x;
    const __half *B1, *B2;
    __half* C; int ldc, z = 0, bm, bn;
    if (EXPERT) {
        z = bid >> 8; int rem = bid & 255; bm = rem >> 3; bn = rem & 7;
        if (bm * BM >= d_cnt[z]) return;
        B1 = guT + (long long)z * 2 * HDIM * CDIM + (long long)(bn * 64) * CDIM;
        B2 = B1 + (long long)HDIM * CDIM;
        C  = hid + (long long)z * NTOK * HDIM;
        ldc = HDIM;
    } else {
        bm = bid >> 5; bn = bid & 31;
        B1 = sgw + (long long)(bn * 64) * CDIM;
        B2 = suw + (long long)(bn * 64) * CDIM;
        C  = sh;
        ldc = HSDIM;
    }
    const int K = CDIM;

    extern __shared__ __align__(16) __half smem[];
    __half* sA = smem;
    __half* sB = smem + 2 * STGH;

    const int tid = threadIdx.x, lane = tid & 31, w = tid >> 5;
    const int ly = lane >> 2, lx = lane & 3;
    const int wm = w >> 1, wn = w & 1;

    const __half* aPtr[8];
    const __half* bPtr[8];
    const int rbase = tid >> 3, kc = (tid & 7) * 8;
#pragma unroll
    for (int c = 0; c < 8; c++) {
        int row = rbase + 16 * c;
        long long arow = EXPERT ? (long long)d_tok[z][bm * BM + row] : (long long)(bm * BM + row);
        aPtr[c] = xr + arow * K;
        bPtr[c] = ((row < 64) ? (B1 + (long long)row * K) : (B2 + (long long)(row - 64) * K));
    }
    auto loadStage = [&](int st, int k0) {
        __half* dA = sA + st * STGH;
        __half* dB = sB + st * STGH;
#pragma unroll
        for (int c = 0; c < 8; c++) {
            int row = rbase + 16 * c;
            cp16(dA + row * AST2 + kc, aPtr[c] + k0 + kc);
            cp16(dB + row * AST2 + kc, bPtr[c] + k0 + kc);
        }
        asm volatile("cp.async.commit_group;");
    };

    float accG[4][4][4], accU[4][4][4];
#pragma unroll
    for (int a = 0; a < 4; a++)
#pragma unroll
        for (int b = 0; b < 4; b++)
#pragma unroll
            for (int q = 0; q < 4; q++) { accG[a][b][q] = 0.f; accU[a][b][q] = 0.f; }

    const int nk = K / BKH;
    loadStage(0, 0);

    for (int kt = 0; kt < nk; kt++) {
        const int st = kt & 1;
        asm volatile("cp.async.wait_group 0;");
        __syncthreads();
        if (kt + 1 < nk) loadStage((kt + 1) & 1, (kt + 1) * BKH);

        const __half* cA = sA + st * STGH;
        const __half* cB = sB + st * STGH;
#pragma unroll
        for (int kg = 0; kg < 4; kg++) {
            const int kb = kg * 16 + lx * 4;
            uint32_t af[4][4], bg[4][2], bu[4][2];
#pragma unroll
            for (int im = 0; im < 4; im++) {
                int r = wm * 64 + im * 16;
                uint2 v0 = *(const uint2*)(cA + (r     + ly) * AST2 + kb);
                uint2 v1 = *(const uint2*)(cA + (r + 8 + ly) * AST2 + kb);
                af[im][0] = v0.x; af[im][1] = v1.x; af[im][2] = v0.y; af[im][3] = v1.y;
            }
#pragma unroll
            for (int in = 0; in < 4; in++) {
                int cn = wn * 32 + in * 8 + ly;
                uint2 g = *(const uint2*)(cB + cn * AST2 + kb);
                uint2 u = *(const uint2*)(cB + (64 + cn) * AST2 + kb);
                bg[in][0] = g.x; bg[in][1] = g.y;
                bu[in][0] = u.x; bu[in][1] = u.y;
            }
#pragma unroll
            for (int im = 0; im < 4; im++)
#pragma unroll
                for (int in = 0; in < 4; in++) {
                    mma16(accG[im][in], af[im], bg[in]);
                    mma16(accU[im][in], af[im], bu[in]);
                }
        }
    }

    // epilogue: out = fp16(silu(g)*u), perm16 layout
#pragma unroll
    for (int im = 0; im < 4; im++) {
        int rr = bm * BM + wm * 64 + im * 16 + ly;
#pragma unroll
        for (int in = 0; in < 4; in++) {
            int G   = wn * 2 + (in >> 1);
            int pos = lx * 4 + (in & 1) * 2;
            long long off = (long long)rr * ldc + bn * 64 + G * 16 + pos;
            float* g = accG[im][in];
            float* u = accU[im][in];
            *(uint32_t*)(C + off)             = h2u(silu_f(g[0]) * u[0], silu_f(g[1]) * u[1]);
            *(uint32_t*)(C + off + 8LL * ldc) = h2u(silu_f(g[2]) * u[2], silu_f(g[3]) * u[3]);
        }
    }
}

// ---------------- phase 2: down GEMMs (fp16, templated expert/shared) ------------
template <bool EXPERT>
__global__ __launch_bounds__(128) void phase2_kernel(
    const __half* __restrict__ hid, const __half* __restrict__ dwT,
    const __half* __restrict__ sh,  const __half* __restrict__ sdw,
    __half* __restrict__ pairh, float* __restrict__ out)
{
    const int bid = blockIdx.x;
    const __half *A, *B; const float* gate;
    __half* Ch = nullptr; float* Cf = nullptr;
    int K, z = 0, bm, bn;
    if (EXPERT) {
        z = bid >> 8; int rem = bid & 255; bm = rem >> 3; bn = rem & 7;
        if (bm * BM >= d_cnt[z]) return;
        A = hid + (long long)z * NTOK * HDIM;
        K = HDIM;
        B = dwT + (long long)z * CDIM * HDIM + (long long)(bn * 128) * HDIM;
        Ch = pairh + (long long)z * NTOK * CDIM;
        gate = d_gate[z];
    } else {
        bm = bid >> 3; bn = bid & 7;
        A = sh; K = HSDIM;
        B = sdw + (long long)(bn * 128) * HSDIM;
        Cf = out;
        gate = nullptr;
    }

    extern __shared__ __align__(16) __half smem[];
    __half* sA = smem;
    __half* sB = smem + 2 * STGH;

    const int tid = threadIdx.x, lane = tid & 31, w = tid >> 5;
    const int ly = lane >> 2, lx = lane & 3;
    const int wm = w >> 1, wn = w & 1;

    const int rbase = tid >> 3, kc = (tid & 7) * 8;
    const __half* aBase = A + (long long)(bm * BM + rbase) * K;
    const __half* bBase = B + (long long)rbase * K;

    auto loadStage = [&](int st, int k0) {
        __half* dA = sA + st * STGH;
        __half* dB = sB + st * STGH;
#pragma unroll
        for (int c = 0; c < 8; c++) {
            int row = rbase + 16 * c;
            cp16(dA + row * AST2 + kc, aBase + (long long)(16 * c) * K + k0 + kc);
            cp16(dB + row * AST2 + kc, bBase + (long long)(16 * c) * K + k0 + kc);
        }
        asm volatile("cp.async.commit_group;");
    };

    float acc[4][8][4];
#pragma unroll
    for (int a = 0; a < 4; a++)
#pragma unroll
        for (int b = 0; b < 8; b++)
#pragma unroll
            for (int q = 0; q < 4; q++) acc[a][b][q] = 0.f;

    const int nk = K / BKH;
    loadStage(0, 0);

    for (int kt = 0; kt < nk; kt++) {
        const int st = kt & 1;
        asm volatile("cp.async.wait_group 0;");
        __syncthreads();
        if (kt + 1 < nk) loadStage((kt + 1) & 1, (kt + 1) * BKH);

        const __half* cA = sA + st * STGH;
        const __half* cB = sB + st * STGH;
#pragma unroll
        for (int kg = 0; kg < 4; kg++) {
            const int kb = kg * 16 + lx * 4;
            uint32_t af[4][4], bf[8][2];
#pragma unroll
            for (int im = 0; im < 4; im++) {
                int r = wm * 64 + im * 16;
                uint2 v0 = *(const uint2*)(cA + (r     + ly) * AST2 + kb);
                uint2 v1 = *(const uint2*)(cA + (r + 8 + ly) * AST2 + kb);
                af[im][0] = v0.x; af[im][1] = v1.x; af[im][2] = v0.y; af[im][3] = v1.y;
            }
#pragma unroll
            for (int in = 0; in < 8; in++) {
                int cn = wn * 64 + in * 8 + ly;
                uint2 bb = *(const uint2*)(cB + cn * AST2 + kb);
                bf[in][0] = bb.x; bf[in][1] = bb.y;
            }
#pragma unroll
            for (int im = 0; im < 4; im++)
#pragma unroll
                for (int in = 0; in < 8; in++)
                    mma16(acc[im][in], af[im], bf[in]);
        }
    }

#pragma unroll
    for (int im = 0; im < 4; im++) {
        int rr = bm * BM + wm * 64 + im * 16 + ly;
        float s0 = gate ? gate[rr] : 1.f;
        float s1 = gate ? gate[rr + 8] : 1.f;
#pragma unroll
        for (int in = 0; in < 8; in++) {
            long long base = (long long)rr * CDIM + bn * 128 + wn * 64 + in * 8 + lx * 2;
            if (EXPERT) {
                *(uint32_t*)(Ch + base)              = h2u(acc[im][in][0] * s0, acc[im][in][1] * s0);
                *(uint32_t*)(Ch + base + 8LL * CDIM) = h2u(acc[im][in][2] * s1, acc[im][in][3] * s1);
            } else {
                *(float2*)(Cf + base)              = make_float2(acc[im][in][0], acc[im][in][1]);
                *(float2*)(Cf + base + 8LL * CDIM) = make_float2(acc[im][in][2], acc[im][in][3]);
            }
        }
    }
}

// ---------------- final combine: out += gated expert pair (fp16 pair) -----------
__global__ void combine_kernel(float* __restrict__ out, const __half* __restrict__ ph) {
    long long i = (long long)blockIdx.x * 256 + threadIdx.x;   // float4 over out
    int t = (int)(i >> 8), j = (int)(i & 255);
    int es0 = d_eslot[t][0], es1 = d_eslot[t][1];
    float4 o = ((float4*)out)[i];
    uint2 q0 = ((const uint2*)(ph + (long long)es0 * CDIM))[j];
    uint2 q1 = ((const uint2*)(ph + (long long)es1 * CDIM))[j];
    float2 a0 = __half22float2(*(__half2*)&q0.x), b0 = __half22float2(*(__half2*)&q0.y);
    float2 a1 = __half22float2(*(__half2*)&q1.x), b1 = __half22float2(*(__half2*)&q1.y);
    o.x += a0.x + a1.x; o.y += a0.y + a1.y;
    o.z += b0.x + b1.x; o.w += b0.y + b1.y;
    ((float4*)out)[i] = o;
}

// ---------------- launch ----------------
extern "C" void kernel_launch(void* const* d_in, const int* in_sizes, int n_in,
                              void* d_out, int out_size) {
    const float* x   = (const float*)d_in[0];
    const float* rw  = (const float*)d_in[1];
    const float* guw = (const float*)d_in[2];
    const float* dw  = (const float*)d_in[3];
    const float* sgw = (const float*)d_in[4];
    const float* suw = (const float*)d_in[5];
    const float* sdw = (const float*)d_in[6];
    float* out = (float*)d_out;

    void* a;
    __half *p_hid, *p_pairh, *p_sh, *p_xr, *p_guT, *p_dwT, *p_sgwr, *p_suwr, *p_sdwr;
    cudaGetSymbolAddress(&a, d_hid);   p_hid   = (__half*)a;
    cudaGetSymbolAddress(&a, d_pairh); p_pairh = (__half*)a;
    cudaGetSymbolAddress(&a, d_sh);    p_sh    = (__half*)a;
    cudaGetSymbolAddress(&a, d_xr);    p_xr    = (__half*)a;
    cudaGetSymbolAddress(&a, d_guT);   p_guT   = (__half*)a;
    cudaGetSymbolAddress(&a, d_dwT);   p_dwT   = (__half*)a;
    cudaGetSymbolAddress(&a, d_sgwr);  p_sgwr  = (__half*)a;
    cudaGetSymbolAddress(&a, d_suwr);  p_suwr  = (__half*)a;
    cudaGetSymbolAddress(&a, d_sdwr);  p_sdwr  = (__half*)a;
    void* cntAddr; cudaGetSymbolAddress(&cntAddr, d_cnt);

    static cudaStream_t s1 = nullptr, s2 = nullptr;
    static cudaEvent_t ev0 = nullptr, evG = nullptr, evD = nullptr, evP = nullptr,
                       evR = nullptr, evS = nullptr;
    if (!s1) {
        cudaStreamCreateWithFlags(&s1, cudaStreamNonBlocking);
        cudaStreamCreateWithFlags(&s2, cudaStreamNonBlocking);
        cudaEventCreateWithFlags(&ev0, cudaEventDisableTiming);
        cudaEventCreateWithFlags(&evG, cudaEventDisableTiming);
        cudaEventCreateWithFlags(&evD, cudaEventDisableTiming);
        cudaEventCreateWithFlags(&evP, cudaEventDisableTiming);
        cudaEventCreateWithFlags(&evR, cudaEventDisableTiming);
        cudaEventCreateWithFlags(&evS, cudaEventDisableTiming);
        cudaFuncSetAttribute(phase1_kernel<true >, cudaFuncAttributeMaxDynamicSharedMemorySize, SMEMB);
        cudaFuncSetAttribute(phase1_kernel<false>, cudaFuncAttributeMaxDynamicSharedMemorySize, SMEMB);
        cudaFuncSetAttribute(phase2_kernel<true >, cudaFuncAttributeMaxDynamicSharedMemorySize, SMEMB);
        cudaFuncSetAttribute(phase2_kernel<false>, cudaFuncAttributeMaxDynamicSharedMemorySize, SMEMB);
    }

    // ---- fork point ----
    cudaEventRecord(ev0, 0);
    cudaStreamWaitEvent(s1, ev0, 0);

    // side stream s1: ordered so earliest consumers unblock first
    transpose_h_perm<<<dim3(2 * HDIM / 32, CDIM / 32, ENUM), dim3(32, 8), 0, s1>>>(guw, p_guT, CDIM, 2 * HDIM);
    cudaEventRecord(evG, s1);
    round_perm3<<<dim3(HSDIM * CDIM / 16 / 256, 3), 256, 0, s1>>>(sgw, p_sgwr, suw, p_suwr, sdw, p_sdwr);
    cudaEventRecord(evP, s1);
    transpose_h_perm<<<dim3(CDIM / 32, HDIM / 32, ENUM), dim3(32, 8), 0, s1>>>(dw, p_dwT, HDIM, CDIM);
    cudaEventRecord(evD, s1);

    // main stream: router (smem-staged rw; emits fp16-perm x + routing tables)
    cudaMemsetAsync(cntAddr, 0, sizeof(int) * ENUM, 0);
    router_kernel<<<NTOK / 32, 256, 0, 0>>>(x, rw, p_xr);
    cudaEventRecord(evR, 0);

    // expert chain on main stream: p1e -> p2e
    cudaStreamWaitEvent(0, evG, 0);
    phase1_kernel<true><<<2048, 128, SMEMB, 0>>>(p_xr, p_guT, p_sgwr, p_suwr, p_hid, p_sh);
    cudaStreamWaitEvent(0, evD, 0);
    phase2_kernel<true><<<2048, 128, SMEMB, 0>>>(p_hid, p_dwT, p_sh, p_sdwr, p_pairh, out);

    // shared chain on s2: p1s -> p2s (writes out base)
    cudaStreamWaitEvent(s2, evR, 0);
    cudaStreamWaitEvent(s2, evP, 0);
    phase1_kernel<false><<<1024, 128, SMEMB, s2>>>(p_xr, p_guT, p_sgwr, p_suwr, p_hid, p_sh);
    phase2_kernel<false><<<256, 128, SMEMB, s2>>>(p_hid, p_dwT, p_sh, p_sdwr, p_pairh, out);
    cudaEventRecord(evS, s2);

    // ---- join: combine after both chains ----
    cudaStreamWaitEvent(0, evS, 0);
    combine_kernel<<<NTOK * CDIM / 4 / 256, 256, 0, 0>>>(out, p_pairh);

    (void)in_sizes; (void)n_in; (void)out_size;
}